// round 1
// baseline (speedup 1.0000x reference)
#include <cuda_runtime.h>
#include <cstdint>

// Problem constants (from reference): N=200000, D=128, K=512.
// Scratch as __device__ globals (no allocation allowed).
#define D_DIM 128
#define MAX_N 200064
#define MAX_K 512

__device__ float g_sums[MAX_K * D_DIM];
__device__ int   g_counts[MAX_K];
__device__ int   g_assign[MAX_N];
__device__ float g_c2[MAX_K];
__device__ float g_f2[MAX_N];

// ---------------------------------------------------------------------------
// Zero the accumulators (graph replays need this every launch).
// ---------------------------------------------------------------------------
__global__ void zero_kernel(int KD, int K) {
    int i = blockIdx.x * blockDim.x + threadIdx.x;
    if (i < KD) g_sums[i] = 0.0f;
    if (i < K)  g_counts[i] = 0;
}

// ---------------------------------------------------------------------------
// c2[k] = sum_d C[k][d]^2 : one warp per center, float4 loads, shfl reduce.
// ---------------------------------------------------------------------------
__global__ void c2_kernel(const float* __restrict__ C, int K) {
    int w = (blockIdx.x * blockDim.x + threadIdx.x) >> 5;
    int lane = threadIdx.x & 31;
    if (w >= K) return;
    float4 v = reinterpret_cast<const float4*>(C + (size_t)w * D_DIM)[lane];
    float s = v.x * v.x + v.y * v.y + v.z * v.z + v.w * v.w;
    #pragma unroll
    for (int o = 16; o > 0; o >>= 1) s += __shfl_xor_sync(0xffffffffu, s, o);
    if (lane == 0) g_c2[w] = s;
}

// ---------------------------------------------------------------------------
// f2[p] = sum_d F[p][d]^2 : one warp per point.
// ---------------------------------------------------------------------------
__global__ void f2_kernel(const float* __restrict__ F, int N) {
    int w = (blockIdx.x * blockDim.x + threadIdx.x) >> 5;
    int lane = threadIdx.x & 31;
    if (w >= N) return;
    float4 v = reinterpret_cast<const float4*>(F + (size_t)w * D_DIM)[lane];
    float s = v.x * v.x + v.y * v.y + v.z * v.z + v.w * v.w;
    #pragma unroll
    for (int o = 16; o > 0; o >>= 1) s += __shfl_xor_sync(0xffffffffu, s, o);
    if (lane == 0) g_f2[w] = s;
}

// ---------------------------------------------------------------------------
// Assignment kernel: tiled N x K "GEMM" with on-the-fly argmin.
//   Block = 128 threads, tile = 64 points x 64 centers, D chunked by 16.
//   Thread (pt = tid>>3 in 0..15, ct = tid&7 in 0..7) computes 4 points x 8
//   centers. Score = (f2 - 2*dot) + c2  (mirrors the reference formula in
//   fp32; 2*dot is exact, so f2 - 2*dot fuses to one rounding either way).
//   Per-point min is reduced across the 8 ct-lanes (consecutive in a warp).
// ---------------------------------------------------------------------------
__global__ __launch_bounds__(128) void assign_kernel(
    const float* __restrict__ F, const float* __restrict__ C, int N, int K)
{
    __shared__ float sF[16][66];   // [d within chunk][point within tile] (+2 pad)
    __shared__ float sC[16][66];   // [d within chunk][center within tile]

    const int tid = threadIdx.x;
    const int pt  = tid >> 3;      // 0..15 point group
    const int ct  = tid & 7;       // 0..7  center group
    const int p0  = blockIdx.x * 64;
    const int lr  = tid >> 2;      // loader row 0..31
    const int lq  = tid & 3;       // loader col group 0..3

    float f2v[4];
    #pragma unroll
    for (int i = 0; i < 4; i++) {
        int p = p0 + pt + 16 * i;
        if (p >= N) p = N - 1;
        f2v[i] = g_f2[p];
    }

    float bestv[4];
    int   besti[4];
    #pragma unroll
    for (int i = 0; i < 4; i++) { bestv[i] = __int_as_float(0x7f800000); besti[i] = 0; }

    for (int k0 = 0; k0 < K; k0 += 64) {
        float acc[4][8];
        #pragma unroll
        for (int i = 0; i < 4; i++)
            #pragma unroll
            for (int j = 0; j < 8; j++) acc[i][j] = 0.0f;

        for (int d0 = 0; d0 < D_DIM; d0 += 16) {
            __syncthreads();
            #pragma unroll
            for (int rr = 0; rr < 2; ++rr) {
                int r = lr + 32 * rr;
                int p = p0 + r; if (p >= N) p = N - 1;
                float4 v = *reinterpret_cast<const float4*>(
                    F + (size_t)p * D_DIM + d0 + lq * 4);
                sF[lq * 4 + 0][r] = v.x;
                sF[lq * 4 + 1][r] = v.y;
                sF[lq * 4 + 2][r] = v.z;
                sF[lq * 4 + 3][r] = v.w;

                int k = k0 + r; if (k >= K) k = K - 1;
                float4 w = *reinterpret_cast<const float4*>(
                    C + (size_t)k * D_DIM + d0 + lq * 4);
                sC[lq * 4 + 0][r] = w.x;
                sC[lq * 4 + 1][r] = w.y;
                sC[lq * 4 + 2][r] = w.z;
                sC[lq * 4 + 3][r] = w.w;
            }
            __syncthreads();

            #pragma unroll
            for (int d = 0; d < 16; ++d) {
                float fv0 = sF[d][pt];
                float fv1 = sF[d][pt + 16];
                float fv2 = sF[d][pt + 32];
                float fv3 = sF[d][pt + 48];
                float cv[8];
                #pragma unroll
                for (int j = 0; j < 8; j++) cv[j] = sC[d][ct + 8 * j];
                #pragma unroll
                for (int j = 0; j < 8; j++) {
                    acc[0][j] = fmaf(fv0, cv[j], acc[0][j]);
                    acc[1][j] = fmaf(fv1, cv[j], acc[1][j]);
                    acc[2][j] = fmaf(fv2, cv[j], acc[2][j]);
                    acc[3][j] = fmaf(fv3, cv[j], acc[3][j]);
                }
            }
        }

        #pragma unroll
        for (int j = 0; j < 8; j++) {
            int k = k0 + ct + 8 * j;
            if (k < K) {
                float c2k = g_c2[k];
                #pragma unroll
                for (int i = 0; i < 4; i++) {
                    float s = (f2v[i] - 2.0f * acc[i][j]) + c2k;
                    if (s < bestv[i]) { bestv[i] = s; besti[i] = k; }
                }
            }
        }
    }

    // Reduce min across the 8 ct-lanes (consecutive lanes in one warp).
    #pragma unroll
    for (int i = 0; i < 4; i++) {
        float v = bestv[i];
        int   ix = besti[i];
        #pragma unroll
        for (int off = 4; off > 0; off >>= 1) {
            float ov = __shfl_down_sync(0xffffffffu, v, off, 8);
            int   oi = __shfl_down_sync(0xffffffffu, ix, off, 8);
            if (ov < v || (ov == v && oi < ix)) { v = ov; ix = oi; }
        }
        if (ct == 0) {
            int p = p0 + pt + 16 * i;
            if (p < N) g_assign[p] = ix;
        }
    }
}

// ---------------------------------------------------------------------------
// Segment sums: one warp per point; lanes cover D with float4; fp32 atomics
// for sums (addresses spread over 128 consecutive floats), int atomic counts.
// ---------------------------------------------------------------------------
__global__ void seg_kernel(const float* __restrict__ F, int N) {
    int w = (blockIdx.x * blockDim.x + threadIdx.x) >> 5;
    int lane = threadIdx.x & 31;
    if (w >= N) return;
    int a = g_assign[w];
    float4 v = reinterpret_cast<const float4*>(F + (size_t)w * D_DIM)[lane];
    float* dst = g_sums + (size_t)a * D_DIM + lane * 4;
    atomicAdd(dst + 0, v.x);
    atomicAdd(dst + 1, v.y);
    atomicAdd(dst + 2, v.z);
    atomicAdd(dst + 3, v.w);
    if (lane == 0) atomicAdd(&g_counts[a], 1);
}

// ---------------------------------------------------------------------------
// Finalize: out[0:KD) = sums/max(count,1);  out[KD:KD+nA) = (float)assign.
// ---------------------------------------------------------------------------
__global__ void final_kernel(float* __restrict__ out, int KD, int nAssign) {
    int i = blockIdx.x * blockDim.x + threadIdx.x;
    if (i < KD) {
        float c = (float)g_counts[i / D_DIM];
        out[i] = g_sums[i] / fmaxf(c, 1.0f);
    } else {
        int a = i - KD;
        if (a < nAssign) out[KD + a] = (float)g_assign[a];
    }
}

// ---------------------------------------------------------------------------
extern "C" void kernel_launch(void* const* d_in, const int* in_sizes, int n_in,
                              void* d_out, int out_size)
{
    const float* F = (const float*)d_in[0];
    const float* C = (const float*)d_in[1];
    const int D = D_DIM;
    const int N = in_sizes[0] / D;
    const int K = in_sizes[1] / D;
    float* out = (float*)d_out;

    const int KD = K * D;

    zero_kernel<<<(KD + 255) / 256, 256>>>(KD, K);
    c2_kernel<<<(K + 7) / 8, 256>>>(C, K);
    f2_kernel<<<(N + 7) / 8, 256>>>(F, N);
    assign_kernel<<<(N + 63) / 64, 128>>>(F, C, N, K);
    seg_kernel<<<(N + 7) / 8, 256>>>(F, N);

    // Output layout: new_centers first, then assign (as float), clipped to
    // whatever out_size actually provides.
    int centersPart, assignPart;
    if (out_size >= KD + N)      { centersPart = KD; assignPart = N; }
    else if (out_size >= KD)     { centersPart = KD; assignPart = out_size - KD; }
    else                         { centersPart = 0;  assignPart = out_size; }
    int total = centersPart + assignPart;
    if (total > 0)
        final_kernel<<<(total + 255) / 256, 256>>>(out, centersPart, assignPart);
}

// round 3
// speedup vs baseline: 1.7825x; 1.7825x over previous
#include <cuda_runtime.h>
#include <cstdint>

#define D_DIM 128
#define MAX_N 200064
#define MAX_K 512

typedef unsigned long long u64;

__device__ float g_sums[MAX_K * D_DIM];
__device__ int   g_counts[MAX_K];
__device__ int   g_assign[MAX_N];
__device__ float g_c2[MAX_K];
__device__ float g_f2[MAX_N];

// ---------------- f32x2 helpers (sm_103a packed fp32) ----------------------
__device__ __forceinline__ u64 pack_dup(float c) {
    u64 r;
    asm("mov.b64 %0, {%1, %1};" : "=l"(r) : "f"(c));
    return r;
}
__device__ __forceinline__ void ffma2(u64& acc, u64 a, u64 b) {
    asm("fma.rn.f32x2 %0, %1, %2, %0;" : "+l"(acc) : "l"(a), "l"(b));
}
__device__ __forceinline__ void unpack2(u64 v, float& lo, float& hi) {
    asm("mov.b64 {%0, %1}, %2;" : "=f"(lo), "=f"(hi) : "l"(v));
}

// ---------------------------------------------------------------------------
__global__ void zero_kernel(int KD, int K) {
    int i = blockIdx.x * blockDim.x + threadIdx.x;
    if (i < KD) g_sums[i] = 0.0f;
    if (i < K)  g_counts[i] = 0;
}

__global__ void c2_kernel(const float* __restrict__ C, int K) {
    int w = (blockIdx.x * blockDim.x + threadIdx.x) >> 5;
    int lane = threadIdx.x & 31;
    if (w >= K) return;
    float4 v = reinterpret_cast<const float4*>(C + (size_t)w * D_DIM)[lane];
    float s = v.x * v.x + v.y * v.y + v.z * v.z + v.w * v.w;
    #pragma unroll
    for (int o = 16; o > 0; o >>= 1) s += __shfl_xor_sync(0xffffffffu, s, o);
    if (lane == 0) g_c2[w] = s;
}

__global__ void f2_kernel(const float* __restrict__ F, int N) {
    int w = (blockIdx.x * blockDim.x + threadIdx.x) >> 5;
    int lane = threadIdx.x & 31;
    if (w >= N) return;
    float4 v = reinterpret_cast<const float4*>(F + (size_t)w * D_DIM)[lane];
    float s = v.x * v.x + v.y * v.y + v.z * v.z + v.w * v.w;
    #pragma unroll
    for (int o = 16; o > 0; o >>= 1) s += __shfl_xor_sync(0xffffffffu, s, o);
    if (lane == 0) g_f2[w] = s;
}

// ---------------------------------------------------------------------------
// Assignment: 128 points x 128 centers per block (256 threads), 8x8 microtile,
// D chunked by 8, shared transposed [d][row] stride 132 (16B-aligned rows,
// conflict-free). Accumulate with packed fma.rn.f32x2 (point-pairs).
// ---------------------------------------------------------------------------
#define SPITCH 132

__global__ __launch_bounds__(256) void assign_kernel(
    const float* __restrict__ F, const float* __restrict__ C, int N, int K)
{
    __shared__ float sF[8 * SPITCH];
    __shared__ float sC[8 * SPITCH];

    const int tid = threadIdx.x;
    const int tx  = tid & 15;          // center group 0..15
    const int ty  = tid >> 4;          // point  group 0..15
    const int tx4 = tx * 4;
    const int ty4 = ty * 4;
    const int p0  = blockIdx.x * 128;

    // loader coords
    const int lr  = tid >> 1;          // 0..127 row
    const int lc4 = (tid & 1) * 4;     // 0 or 4 (col group)
    int prow = p0 + lr; if (prow >= N) prow = N - 1;
    const float* Fld = F + (size_t)prow * D_DIM + lc4;

    // f2 for my 8 point slots (slots 0..3 -> ty4+s, 4..7 -> 64+ty4+s-4)
    float f2v[8];
    #pragma unroll
    for (int s = 0; s < 8; s++) {
        int p = p0 + ((s < 4) ? (ty4 + s) : (64 + ty4 + s - 4));
        if (p >= N) p = N - 1;
        f2v[s] = g_f2[p];
    }

    float bestv[8];
    int   besti[8];
    #pragma unroll
    for (int s = 0; s < 8; s++) { bestv[s] = __int_as_float(0x7f800000); besti[s] = 0; }

    u64 acc[4][8];
    #pragma unroll
    for (int i = 0; i < 4; i++)
        #pragma unroll
        for (int j = 0; j < 8; j++) acc[i][j] = 0ULL;

    const int nkt = K >> 7;            // k-tiles of 128
    const int it_total = nkt * 16;     // 16 d-chunks each

    // prefetch iteration 0
    float4 vF = *reinterpret_cast<const float4*>(Fld);
    float4 vC = *reinterpret_cast<const float4*>(C + (size_t)lr * D_DIM + lc4);

    for (int it = 0; it < it_total; ++it) {
        __syncthreads();
        // store prefetched chunk (transposed)
        {
            float* dF = sF + lc4 * SPITCH + lr;
            dF[0 * SPITCH] = vF.x; dF[1 * SPITCH] = vF.y;
            dF[2 * SPITCH] = vF.z; dF[3 * SPITCH] = vF.w;
            float* dC = sC + lc4 * SPITCH + lr;
            dC[0 * SPITCH] = vC.x; dC[1 * SPITCH] = vC.y;
            dC[2 * SPITCH] = vC.z; dC[3 * SPITCH] = vC.w;
        }
        __syncthreads();

        // prefetch next chunk
        if (it + 1 < it_total) {
            int nit = it + 1;
            int ch  = nit & 15;
            int kt  = nit >> 4;
            vF = *reinterpret_cast<const float4*>(Fld + ch * 8);
            vC = *reinterpret_cast<const float4*>(
                C + (size_t)(kt * 128 + lr) * D_DIM + ch * 8 + lc4);
        }

        // compute this chunk: 8 d-slices
        #pragma unroll
        for (int d = 0; d < 8; ++d) {
            const float* rowF = sF + d * SPITCH;
            const float* rowC = sC + d * SPITCH;
            ulonglong2 a0 = *reinterpret_cast<const ulonglong2*>(rowF + ty4);
            ulonglong2 a1 = *reinterpret_cast<const ulonglong2*>(rowF + 64 + ty4);
            float4 c0 = *reinterpret_cast<const float4*>(rowC + tx4);
            float4 c1 = *reinterpret_cast<const float4*>(rowC + 64 + tx4);
            u64 cc[8];
            cc[0] = pack_dup(c0.x); cc[1] = pack_dup(c0.y);
            cc[2] = pack_dup(c0.z); cc[3] = pack_dup(c0.w);
            cc[4] = pack_dup(c1.x); cc[5] = pack_dup(c1.y);
            cc[6] = pack_dup(c1.z); cc[7] = pack_dup(c1.w);
            #pragma unroll
            for (int j = 0; j < 8; j++) {
                ffma2(acc[0][j], a0.x, cc[j]);
                ffma2(acc[1][j], a0.y, cc[j]);
                ffma2(acc[2][j], a1.x, cc[j]);
                ffma2(acc[3][j], a1.y, cc[j]);
            }
        }

        // end of a k-tile: score + argmin, reset accumulators
        if ((it & 15) == 15) {
            int kt = it >> 4;
            #pragma unroll
            for (int j = 0; j < 8; j++) {
                int k = kt * 128 + ((j < 4) ? (tx4 + j) : (64 + tx4 + j - 4));
                float c2k = (k < K) ? g_c2[k] : __int_as_float(0x7f800000);
                #pragma unroll
                for (int pi = 0; pi < 4; pi++) {
                    float lo, hi;
                    unpack2(acc[pi][j], lo, hi);
                    int s0 = (pi >> 1) * 4 + (pi & 1) * 2;
                    float sc0 = (f2v[s0]     - 2.0f * lo) + c2k;
                    float sc1 = (f2v[s0 + 1] - 2.0f * hi) + c2k;
                    if (sc0 < bestv[s0])     { bestv[s0]     = sc0; besti[s0]     = k; }
                    if (sc1 < bestv[s0 + 1]) { bestv[s0 + 1] = sc1; besti[s0 + 1] = k; }
                    acc[pi][j] = 0ULL;
                }
            }
        }
    }

    // reduce across the 16 tx lanes (contiguous within half-warp)
    #pragma unroll
    for (int s = 0; s < 8; s++) {
        float v  = bestv[s];
        int   ix = besti[s];
        #pragma unroll
        for (int off = 8; off > 0; off >>= 1) {
            float ov = __shfl_down_sync(0xffffffffu, v, off, 16);
            int   oi = __shfl_down_sync(0xffffffffu, ix, off, 16);
            if (ov < v || (ov == v && oi < ix)) { v = ov; ix = oi; }
        }
        if (tx == 0) {
            int p = p0 + ((s < 4) ? (ty4 + s) : (64 + ty4 + s - 4));
            if (p < N) g_assign[p] = ix;
        }
    }
}

// ---------------------------------------------------------------------------
__global__ void seg_kernel(const float* __restrict__ F, int N) {
    int w = (blockIdx.x * blockDim.x + threadIdx.x) >> 5;
    int lane = threadIdx.x & 31;
    if (w >= N) return;
    int a = g_assign[w];
    float4 v = reinterpret_cast<const float4*>(F + (size_t)w * D_DIM)[lane];
    float* dst = g_sums + (size_t)a * D_DIM + lane * 4;
    atomicAdd(dst + 0, v.x);
    atomicAdd(dst + 1, v.y);
    atomicAdd(dst + 2, v.z);
    atomicAdd(dst + 3, v.w);
    if (lane == 0) atomicAdd(&g_counts[a], 1);
}

__global__ void final_kernel(float* __restrict__ out, int KD, int nAssign) {
    int i = blockIdx.x * blockDim.x + threadIdx.x;
    if (i < KD) {
        float c = (float)g_counts[i / D_DIM];
        out[i] = g_sums[i] / fmaxf(c, 1.0f);
    } else {
        int a = i - KD;
        if (a < nAssign) out[KD + a] = (float)g_assign[a];
    }
}

// ---------------------------------------------------------------------------
extern "C" void kernel_launch(void* const* d_in, const int* in_sizes, int n_in,
                              void* d_out, int out_size)
{
    (void)n_in;
    const float* F = (const float*)d_in[0];
    const float* C = (const float*)d_in[1];
    const int D = D_DIM;
    const int N = in_sizes[0] / D;
    const int K = in_sizes[1] / D;
    float* out = (float*)d_out;

    const int KD = K * D;

    zero_kernel<<<(KD + 255) / 256, 256>>>(KD, K);
    c2_kernel<<<(K + 7) / 8, 256>>>(C, K);
    f2_kernel<<<(N + 7) / 8, 256>>>(F, N);
    assign_kernel<<<(N + 127) / 128, 256>>>(F, C, N, K);
    seg_kernel<<<(N + 7) / 8, 256>>>(F, N);

    int centersPart, assignPart;
    if (out_size >= KD + N)      { centersPart = KD; assignPart = N; }
    else if (out_size >= KD)     { centersPart = KD; assignPart = out_size - KD; }
    else                         { centersPart = 0;  assignPart = out_size; }
    int total = centersPart + assignPart;
    if (total > 0)
        final_kernel<<<(total + 255) / 256, 256>>>(out, centersPart, assignPart);
}

// round 4
// speedup vs baseline: 2.5700x; 1.4418x over previous
#include <cuda_runtime.h>
#include <cstdint>

#define D_DIM 128
#define MAX_N 200064
#define MAX_K 512

typedef unsigned long long u64;

__device__ float g_sums[MAX_K * D_DIM];
__device__ int   g_counts[MAX_K];
__device__ int   g_assign[MAX_N];
__device__ float g_c2[MAX_K];
__device__ float g_f2[MAX_N];

// ---------------- f32x2 helpers (sm_103a packed fp32) ----------------------
__device__ __forceinline__ u64 pack_dup(float c) {
    u64 r;
    asm("mov.b64 %0, {%1, %1};" : "=l"(r) : "f"(c));
    return r;
}
__device__ __forceinline__ void ffma2(u64& acc, u64 a, u64 b) {
    asm("fma.rn.f32x2 %0, %1, %2, %0;" : "+l"(acc) : "l"(a), "l"(b));
}
__device__ __forceinline__ void unpack2(u64 v, float& lo, float& hi) {
    asm("mov.b64 {%0, %1}, %2;" : "=f"(lo), "=f"(hi) : "l"(v));
}

// ---------------------------------------------------------------------------
__global__ void zero_kernel(int KD, int K) {
    int i = blockIdx.x * blockDim.x + threadIdx.x;
    if (i < KD) g_sums[i] = 0.0f;
    if (i < K)  g_counts[i] = 0;
}

__global__ void c2_kernel(const float* __restrict__ C, int K) {
    int w = (blockIdx.x * blockDim.x + threadIdx.x) >> 5;
    int lane = threadIdx.x & 31;
    if (w >= K) return;
    float4 v = reinterpret_cast<const float4*>(C + (size_t)w * D_DIM)[lane];
    float s = v.x * v.x + v.y * v.y + v.z * v.z + v.w * v.w;
    #pragma unroll
    for (int o = 16; o > 0; o >>= 1) s += __shfl_xor_sync(0xffffffffu, s, o);
    if (lane == 0) g_c2[w] = s;
}

__global__ void f2_kernel(const float* __restrict__ F, int N) {
    int w = (blockIdx.x * blockDim.x + threadIdx.x) >> 5;
    int lane = threadIdx.x & 31;
    if (w >= N) return;
    float4 v = reinterpret_cast<const float4*>(F + (size_t)w * D_DIM)[lane];
    float s = v.x * v.x + v.y * v.y + v.z * v.z + v.w * v.w;
    #pragma unroll
    for (int o = 16; o > 0; o >>= 1) s += __shfl_xor_sync(0xffffffffu, s, o);
    if (lane == 0) g_f2[w] = s;
}

// ---------------------------------------------------------------------------
// Assignment: 128 points x 128 centers per block (256 threads), 8x8 microtile,
// D chunked by 8, DOUBLE-BUFFERED transposed shared tiles (one sync/chunk),
// packed fma.rn.f32x2 accumulation. __launch_bounds__(256,2) to get 2
// resident blocks per SM (regs <= 128).
// ---------------------------------------------------------------------------
#define SPITCH 132

__global__ __launch_bounds__(256, 2) void assign_kernel(
    const float* __restrict__ F, const float* __restrict__ C, int N, int K)
{
    __shared__ float sF[2][8 * SPITCH];
    __shared__ float sC[2][8 * SPITCH];

    const int tid = threadIdx.x;
    const int tx  = tid & 15;          // center group 0..15
    const int ty  = tid >> 4;          // point  group 0..15
    const int tx4 = tx * 4;
    const int ty4 = ty * 4;
    const int p0  = blockIdx.x * 128;

    // loader coords
    const int lr  = tid >> 1;          // 0..127 row
    const int lc4 = (tid & 1) * 4;     // 0 or 4 (col group)
    int prow = p0 + lr; if (prow >= N) prow = N - 1;
    const float* Fld = F + (size_t)prow * D_DIM + lc4;

    float bestv[8];
    int   besti[8];
    #pragma unroll
    for (int s = 0; s < 8; s++) { bestv[s] = __int_as_float(0x7f800000); besti[s] = 0; }

    u64 acc[4][8];
    #pragma unroll
    for (int i = 0; i < 4; i++)
        #pragma unroll
        for (int j = 0; j < 8; j++) acc[i][j] = 0ULL;

    const int nkt = K >> 7;            // k-tiles of 128
    const int it_total = nkt * 16;     // 16 d-chunks each

    // load + store chunk 0 into buffer 0
    float4 vF = *reinterpret_cast<const float4*>(Fld);
    float4 vC = *reinterpret_cast<const float4*>(C + (size_t)lr * D_DIM + lc4);
    {
        float* dF = sF[0] + lc4 * SPITCH + lr;
        dF[0 * SPITCH] = vF.x; dF[1 * SPITCH] = vF.y;
        dF[2 * SPITCH] = vF.z; dF[3 * SPITCH] = vF.w;
        float* dC = sC[0] + lc4 * SPITCH + lr;
        dC[0 * SPITCH] = vC.x; dC[1 * SPITCH] = vC.y;
        dC[2 * SPITCH] = vC.z; dC[3 * SPITCH] = vC.w;
    }
    __syncthreads();

    for (int it = 0; it < it_total; ++it) {
        const int cur  = it & 1;
        const bool more = (it + 1 < it_total);

        // prefetch next chunk (global -> regs), long latency overlapped with compute
        if (more) {
            int nit = it + 1;
            int ch  = nit & 15;
            int kt  = nit >> 4;
            vF = *reinterpret_cast<const float4*>(Fld + ch * 8);
            vC = *reinterpret_cast<const float4*>(
                C + (size_t)(kt * 128 + lr) * D_DIM + ch * 8 + lc4);
        }

        // compute this chunk: 8 d-slices from buffer `cur`
        #pragma unroll
        for (int d = 0; d < 8; ++d) {
            const float* rowF = sF[cur] + d * SPITCH;
            const float* rowC = sC[cur] + d * SPITCH;
            ulonglong2 a0 = *reinterpret_cast<const ulonglong2*>(rowF + ty4);
            ulonglong2 a1 = *reinterpret_cast<const ulonglong2*>(rowF + 64 + ty4);
            float4 c0 = *reinterpret_cast<const float4*>(rowC + tx4);
            float4 c1 = *reinterpret_cast<const float4*>(rowC + 64 + tx4);
            u64 cc[8];
            cc[0] = pack_dup(c0.x); cc[1] = pack_dup(c0.y);
            cc[2] = pack_dup(c0.z); cc[3] = pack_dup(c0.w);
            cc[4] = pack_dup(c1.x); cc[5] = pack_dup(c1.y);
            cc[6] = pack_dup(c1.z); cc[7] = pack_dup(c1.w);
            #pragma unroll
            for (int j = 0; j < 8; j++) {
                ffma2(acc[0][j], a0.x, cc[j]);
                ffma2(acc[1][j], a0.y, cc[j]);
                ffma2(acc[2][j], a1.x, cc[j]);
                ffma2(acc[3][j], a1.y, cc[j]);
            }
        }

        // store prefetched chunk into the other buffer (safe: previous use of
        // that buffer finished before the sync at the end of it-1)
        if (more) {
            const int nxt = cur ^ 1;
            float* dF = sF[nxt] + lc4 * SPITCH + lr;
            dF[0 * SPITCH] = vF.x; dF[1 * SPITCH] = vF.y;
            dF[2 * SPITCH] = vF.z; dF[3 * SPITCH] = vF.w;
            float* dC = sC[nxt] + lc4 * SPITCH + lr;
            dC[0 * SPITCH] = vC.x; dC[1 * SPITCH] = vC.y;
            dC[2 * SPITCH] = vC.z; dC[3 * SPITCH] = vC.w;
        }
        __syncthreads();

        // end of a k-tile: score + argmin, reset accumulators (f2/c2 loaded
        // lazily here to keep register count <= 128)
        if ((it & 15) == 15) {
            int kt = it >> 4;
            #pragma unroll
            for (int j = 0; j < 8; j++) {
                int k = kt * 128 + ((j < 4) ? (tx4 + j) : (64 + tx4 + j - 4));
                float c2k = (k < K) ? g_c2[k] : __int_as_float(0x7f800000);
                #pragma unroll
                for (int pi = 0; pi < 4; pi++) {
                    float lo, hi;
                    unpack2(acc[pi][j], lo, hi);
                    int s0 = (pi >> 1) * 4 + (pi & 1) * 2;
                    int pA = p0 + ((s0 < 4) ? (ty4 + s0) : (64 + ty4 + s0 - 4));
                    int pB = pA + 1;
                    if (pA >= N) pA = N - 1;
                    if (pB >= N) pB = N - 1;
                    float sc0 = (g_f2[pA] - 2.0f * lo) + c2k;
                    float sc1 = (g_f2[pB] - 2.0f * hi) + c2k;
                    if (sc0 < bestv[s0])     { bestv[s0]     = sc0; besti[s0]     = k; }
                    if (sc1 < bestv[s0 + 1]) { bestv[s0 + 1] = sc1; besti[s0 + 1] = k; }
                    acc[pi][j] = 0ULL;
                }
            }
        }
    }

    // reduce across the 16 tx lanes (contiguous within half-warp)
    #pragma unroll
    for (int s = 0; s < 8; s++) {
        float v  = bestv[s];
        int   ix = besti[s];
        #pragma unroll
        for (int off = 8; off > 0; off >>= 1) {
            float ov = __shfl_down_sync(0xffffffffu, v, off, 16);
            int   oi = __shfl_down_sync(0xffffffffu, ix, off, 16);
            if (ov < v || (ov == v && oi < ix)) { v = ov; ix = oi; }
        }
        if (tx == 0) {
            int p = p0 + ((s < 4) ? (ty4 + s) : (64 + ty4 + s - 4));
            if (p < N) g_assign[p] = ix;
        }
    }
}

// ---------------------------------------------------------------------------
// Segment sums: one warp per point; vector RED (red.global.add.v4.f32) cuts
// LSU/LTS op count 4x vs scalar atomics.
// ---------------------------------------------------------------------------
__global__ void seg_kernel(const float* __restrict__ F, int N) {
    int w = (blockIdx.x * blockDim.x + threadIdx.x) >> 5;
    int lane = threadIdx.x & 31;
    if (w >= N) return;
    int a = g_assign[w];
    float4 v = reinterpret_cast<const float4*>(F + (size_t)w * D_DIM)[lane];
    float* dst = g_sums + (size_t)a * D_DIM + lane * 4;
    asm volatile("red.global.add.v4.f32 [%0], {%1, %2, %3, %4};"
                 :: "l"(dst), "f"(v.x), "f"(v.y), "f"(v.z), "f"(v.w)
                 : "memory");
    if (lane == 0) atomicAdd(&g_counts[a], 1);
}

__global__ void final_kernel(float* __restrict__ out, int KD, int nAssign) {
    int i = blockIdx.x * blockDim.x + threadIdx.x;
    if (i < KD) {
        float c = (float)g_counts[i / D_DIM];
        out[i] = g_sums[i] / fmaxf(c, 1.0f);
    } else {
        int a = i - KD;
        if (a < nAssign) out[KD + a] = (float)g_assign[a];
    }
}

// ---------------------------------------------------------------------------
extern "C" void kernel_launch(void* const* d_in, const int* in_sizes, int n_in,
                              void* d_out, int out_size)
{
    (void)n_in;
    const float* F = (const float*)d_in[0];
    const float* C = (const float*)d_in[1];
    const int D = D_DIM;
    const int N = in_sizes[0] / D;
    const int K = in_sizes[1] / D;
    float* out = (float*)d_out;

    const int KD = K * D;

    zero_kernel<<<(KD + 255) / 256, 256>>>(KD, K);
    c2_kernel<<<(K + 7) / 8, 256>>>(C, K);
    f2_kernel<<<(N + 7) / 8, 256>>>(F, N);
    assign_kernel<<<(N + 127) / 128, 256>>>(F, C, N, K);
    seg_kernel<<<(N + 7) / 8, 256>>>(F, N);

    int centersPart, assignPart;
    if (out_size >= KD + N)      { centersPart = KD; assignPart = N; }
    else if (out_size >= KD)     { centersPart = KD; assignPart = out_size - KD; }
    else                         { centersPart = 0;  assignPart = out_size; }
    int total = centersPart + assignPart;
    if (total > 0)
        final_kernel<<<(total + 255) / 256, 256>>>(out, centersPart, assignPart);
}